// round 13
// baseline (speedup 1.0000x reference)
#include <cuda_runtime.h>
#include <cstdint>
#include <cstddef>

#define LATENT   2000
#define NG       10000
#define KER      20
#define BATCH    128
#define NTILE    80            // groups per CTA; 10000 = 125*80
#define NCTA     125
#define KT       32            // K per tile (f32 elements)
#define NTIL     63            // 2000 = 62*32 + 16 (last tile zero-padded)
#define NSTG     3             // 63 = 21*3
#define PB       80            // staged row pitch bytes (64B bf16 data + 16B pad)
#define SROWS    208           // 128 A rows + 80 B rows
#define STG_BYTES (SROWS*PB)   // 16640
#define HP       81            // h_s pitch

#define OFF_HS   (NSTG*STG_BYTES)        // 49920 : h_s 128*81 f32
#define OFF_RS   (OFF_HS + BATCH*HP*4)   // 91392 : red_s 2*80
#define OFF_RQ   (OFF_RS + 640)          // red_q 2*80
#define OFF_SSC  (OFF_RQ + 640)
#define OFF_SSH  (OFF_SSC + 320)
#define OFF_SCW  (OFF_SSH + 320)         // conv_w 80*20
#define OFF_SCB  (OFF_SCW + 6400)
#define OFF_BAR  (OFF_SCB + 320)         // full[3] + empty[3], 8B each
#define SMEM_BYTES (OFF_BAR + 48)

__device__ __forceinline__ uint32_t packbf(float lo, float hi) {
    uint32_t r;
    asm("cvt.rn.bf16x2.f32 %0, %1, %2;" : "=r"(r) : "f"(hi), "f"(lo));
    return r;
}
__device__ __forceinline__ void mbar_init(uint32_t mbar, uint32_t cnt) {
    asm volatile("mbarrier.init.shared.b64 [%0], %1;\n" :: "r"(mbar), "r"(cnt) : "memory");
}
__device__ __forceinline__ void mbar_arrive(uint32_t mbar) {
    asm volatile("mbarrier.arrive.release.cta.shared::cta.b64 _, [%0];\n"
                 :: "r"(mbar) : "memory");
}
__device__ __forceinline__ void mbar_wait(uint32_t mbar, uint32_t parity) {
    uint32_t done;
    asm volatile(
        "{\n\t.reg .pred p;\n\t"
        "mbarrier.try_wait.parity.acquire.cta.shared::cta.b64 p, [%1], %2;\n\t"
        "selp.b32 %0, 1, 0, p;\n\t}\n"
        : "=r"(done) : "r"(mbar), "r"(parity) : "memory");
    if (!done) {
        asm volatile(
            "{\n\t.reg .pred P1;\n\t"
            "W_%=:\n\t"
            "mbarrier.try_wait.parity.acquire.cta.shared::cta.b64 P1, [%0], %1, 0x989680;\n\t"
            "@P1 bra.uni D_%=;\n\t"
            "bra.uni W_%=;\n\t"
            "D_%=:\n\t}\n"
            :: "r"(mbar), "r"(parity) : "memory");
    }
}
__device__ __forceinline__ void ldsm4(uint32_t* r, uint32_t a) {
    asm volatile("ldmatrix.sync.aligned.m8n8.x4.shared.b16 {%0,%1,%2,%3}, [%4];"
        : "=r"(r[0]), "=r"(r[1]), "=r"(r[2]), "=r"(r[3]) : "r"(a));
}
__device__ __forceinline__ void ldsm2(uint32_t* r, uint32_t a) {
    asm volatile("ldmatrix.sync.aligned.m8n8.x2.shared.b16 {%0,%1}, [%2];"
        : "=r"(r[0]), "=r"(r[1]) : "r"(a));
}
__device__ __forceinline__ void mma16816(float* d, const uint32_t* a,
                                         uint32_t b0, uint32_t b1) {
    asm volatile(
        "mma.sync.aligned.m16n8k16.row.col.f32.bf16.bf16.f32 "
        "{%0,%1,%2,%3}, {%4,%5,%6,%7}, {%8,%9}, {%0,%1,%2,%3};\n"
        : "+f"(d[0]), "+f"(d[1]), "+f"(d[2]), "+f"(d[3])
        : "r"(a[0]), "r"(a[1]), "r"(a[2]), "r"(a[3]), "r"(b0), "r"(b1));
}
__device__ __forceinline__ float sigf(float y) {
    float t;
    asm("tanh.approx.f32 %0, %1;" : "=f"(t) : "f"(0.5f * y));
    return fmaf(0.5f, t, 0.5f);
}

__global__ void __launch_bounds__(512, 1)
fused_decoder(const float* __restrict__ z,
              const float* __restrict__ Wfc,
              const float* __restrict__ gamma,
              const float* __restrict__ beta,
              const float* __restrict__ convw,
              const float* __restrict__ convb,
              float* __restrict__ out)
{
    extern __shared__ float sm[];
    float* h_s    = (float*)((char*)sm + OFF_HS);
    float* red_s  = (float*)((char*)sm + OFF_RS);
    float* red_q  = (float*)((char*)sm + OFF_RQ);
    float* sscale = (float*)((char*)sm + OFF_SSC);
    float* sshift = (float*)((char*)sm + OFF_SSH);
    float* scw    = (float*)((char*)sm + OFF_SCW);
    float* scb    = (float*)((char*)sm + OFF_SCB);

    const int tid  = threadIdx.x;
    const int w    = tid >> 5;
    const int lane = tid & 31;
    const int kq   = lane & 3;
    const int rq   = lane >> 2;
    const int g0   = blockIdx.x * NTILE;

    uint32_t stg_u32;
    asm("{ .reg .u64 t; cvta.to.shared.u64 t, %1; cvt.u32.u64 %0, t; }"
        : "=r"(stg_u32) : "l"(sm));
    const uint32_t barF = stg_u32 + OFF_BAR;       // full[3]
    const uint32_t barE = stg_u32 + OFF_BAR + 24;  // empty[3]

    if (tid == 0) {
        #pragma unroll
        for (int s = 0; s < NSTG; ++s) {
            mbar_init(barF + s * 8, 384);   // producer threads (12 warps)
            mbar_init(barE + s * 8, 128);   // consumer threads (4 warps)
        }
    }
    for (int i = tid; i < NTILE * KER; i += 512)
        scw[i] = convw[(size_t)g0 * KER + i];
    if (tid < NTILE) scb[tid] = convb[g0 + tid];
    __syncthreads();   // mbarrier init + conv params visible

    if (tid >= 128) {
        // ======== producers (warps 4..15, 384 threads): LDG f32 -> cvt bf16 -> STS ========
        const int p = tid - 128;
        const int nch = (p < 128) ? 5 : 4;       // 128*5 + 256*4 = 1664 chunks
        const float* srcp[5];
        uint32_t dstoff[5];
        uint32_t okmask = 0;
        #pragma unroll
        for (int j = 0; j < 5; ++j) {
            const int c = p + j * 384;
            const int cc = (c < 1664) ? c : 0;
            const int row  = cc >> 3;            // 0..207
            const int col8 = cc & 7;             // 4-float sub-column
            srcp[j]  = (row < 128) ? z + (size_t)row * LATENT + col8 * 4
                                   : Wfc + (size_t)(g0 + row - 128) * LATENT + col8 * 4;
            dstoff[j] = (uint32_t)(row * PB + col8 * 8);   // 8B bf16 per chunk
            if (col8 < 4) okmask |= (1u << j);   // k = 1984 + col8*4 < 2000
        }
        float4 fifo[3][5];   // depth-3 register FIFO (producer-path-only registers)
        auto ldg_tile = [&](int t, int s) {
            #pragma unroll
            for (int j = 0; j < 5; ++j) {
                if (j >= nch) break;
                const bool v = (t < NTIL - 1) || ((okmask >> j) & 1);
                fifo[s][j] = v ? *(const float4*)(srcp[j] + (size_t)t * KT)
                               : make_float4(0.f, 0.f, 0.f, 0.f);
            }
        };
        auto sts_tile = [&](int s) {
            char* base = (char*)sm + s * STG_BYTES;
            #pragma unroll
            for (int j = 0; j < 5; ++j) {
                if (j >= nch) break;
                const float4 f = fifo[s][j];
                uint2 u;
                u.x = packbf(f.x, f.y);
                u.y = packbf(f.z, f.w);
                *(uint2*)(base + dstoff[j]) = u;
            }
        };
        ldg_tile(0, 0); ldg_tile(1, 1); ldg_tile(2, 2);
        int ph = 1;   // producer empty-phase starts 1: first NSTG waits pass immediately
        #pragma unroll 1
        for (int tb = 0; tb < 21; ++tb) {
            #pragma unroll
            for (int i = 0; i < 3; ++i) {
                const int t = tb * 3 + i;
                mbar_wait(barE + i * 8, ph);
                sts_tile(i);                      // tile t lives in fifo slot i
                mbar_arrive(barF + i * 8);        // release: STS visible to acquirers
                if (t + 3 < NTIL) ldg_tile(t + 3, i);
            }
            ph ^= 1;
        }
    }

    // ======== consumers (warps 0..3: m64 x n40 each, fragment-pipelined) ========
    const int mb = (w & 1) * 64;          // 2 m-blocks of 64
    const int nh = (w >> 1) * 40;         // 2 n-halves of 40
    const uint32_t aoffb = (uint32_t)(mb + (lane & 15)) * PB + (lane >> 4) * 16;
    const uint32_t boff0 = (uint32_t)(128 + nh + ((lane >> 4) << 3) + (lane & 7)) * PB
                         + ((lane >> 3) & 1) * 16;
    const uint32_t boff1 = boff0 + 16 * PB;
    const uint32_t boff2 = (uint32_t)(128 + nh + 32 + (lane & 7)) * PB
                         + ((lane >> 3) & 1) * 16;

    float d[4][5][4];
    #pragma unroll
    for (int a = 0; a < 4; ++a)
        #pragma unroll
        for (int b = 0; b < 5; ++b)
            #pragma unroll
            for (int c = 0; c < 4; ++c) d[a][b][c] = 0.f;

    if (tid < 128) {
        uint32_t Bf[2][10];   // [ks-buffer][B01:0-3, B23:4-7, B4:8-9]
        uint32_t Af[2][4];    // A fragment double buffer
        int ph = 0;
        #pragma unroll 1
        for (int tb = 0; tb < 21; ++tb) {
            #pragma unroll
            for (int i = 0; i < 3; ++i) {
                mbar_wait(barF + i * 8, ph);
                const uint32_t base = stg_u32 + (uint32_t)i * STG_BYTES;
                // preload ks=0 B frags + A(mt=0)
                ldsm4(Bf[0] + 0, base + boff0);
                ldsm4(Bf[0] + 4, base + boff1);
                ldsm2(Bf[0] + 8, base + boff2);
                ldsm4(Af[0], base + aoffb);
                #pragma unroll
                for (int ks = 0; ks < 2; ++ks) {
                    const uint32_t ko = ks * 32;
                    #pragma unroll
                    for (int mt = 0; mt < 4; ++mt) {
                        uint32_t* cur = Af[mt & 1];
                        uint32_t* nxt = Af[(mt + 1) & 1];
                        if (mt < 3) {
                            ldsm4(nxt, base + aoffb + (uint32_t)((mt + 1) * 16 * PB) + ko);
                        } else if (ks == 0) {
                            ldsm4(Bf[1] + 0, base + boff0 + 32);
                            ldsm4(Bf[1] + 4, base + boff1 + 32);
                            ldsm2(Bf[1] + 8, base + boff2 + 32);
                            ldsm4(nxt, base + aoffb + 32);
                        } else {
                            mbar_arrive(barE + i * 8);   // all stage reads issued
                        }
                        mma16816(d[mt][0], cur, Bf[ks][0], Bf[ks][1]);
                        mma16816(d[mt][1], cur, Bf[ks][2], Bf[ks][3]);
                        mma16816(d[mt][2], cur, Bf[ks][4], Bf[ks][5]);
                        mma16816(d[mt][3], cur, Bf[ks][6], Bf[ks][7]);
                        mma16816(d[mt][4], cur, Bf[ks][8], Bf[ks][9]);
                    }
                }
            }
            ph ^= 1;
        }
    }
    __syncthreads();

    // ======== BatchNorm stats (b_fc cancels under mean subtraction) ========
    if (w < 4) {
        #pragma unroll
        for (int nt = 0; nt < 5; ++nt) {
            float s0 = 0.f, s1 = 0.f, q0 = 0.f, q1 = 0.f;
            #pragma unroll
            for (int mt = 0; mt < 4; ++mt) {
                s0 += d[mt][nt][0] + d[mt][nt][2];
                s1 += d[mt][nt][1] + d[mt][nt][3];
                q0 += d[mt][nt][0]*d[mt][nt][0] + d[mt][nt][2]*d[mt][nt][2];
                q1 += d[mt][nt][1]*d[mt][nt][1] + d[mt][nt][3]*d[mt][nt][3];
            }
            #pragma unroll
            for (int o = 4; o < 32; o <<= 1) {
                s0 += __shfl_xor_sync(0xffffffffu, s0, o);
                s1 += __shfl_xor_sync(0xffffffffu, s1, o);
                q0 += __shfl_xor_sync(0xffffffffu, q0, o);
                q1 += __shfl_xor_sync(0xffffffffu, q1, o);
            }
            if (rq == 0) {
                const int n = nh + nt * 8 + kq * 2;
                red_s[(w & 1) * 80 + n]     = s0;
                red_s[(w & 1) * 80 + n + 1] = s1;
                red_q[(w & 1) * 80 + n]     = q0;
                red_q[(w & 1) * 80 + n + 1] = q1;
            }
        }
    }
    __syncthreads();
    if (tid < NTILE) {
        const float s = red_s[tid] + red_s[80 + tid];
        const float q = red_q[tid] + red_q[80 + tid];
        const float mean = s * (1.f / BATCH);
        const float var  = q * (1.f / BATCH) - mean * mean;
        const float scv  = gamma[g0 + tid] * rsqrtf(var + 1e-5f);
        sscale[tid] = scv;
        sshift[tid] = beta[g0 + tid] - mean * scv;
    }
    __syncthreads();

    // ======== normalize + LeakyReLU -> h_s ========
    if (w < 4) {
        #pragma unroll
        for (int mt = 0; mt < 4; ++mt)
            #pragma unroll
            for (int nt = 0; nt < 5; ++nt)
                #pragma unroll
                for (int c = 0; c < 4; ++c) {
                    const int n = nh + nt * 8 + kq * 2 + (c & 1);
                    const int m = mb + mt * 16 + rq + ((c >> 1) << 3);
                    float hn = d[mt][nt][c] * sscale[n] + sshift[n];
                    hn = fmaxf(hn, 0.1f * hn);
                    h_s[m * HP + n] = hn;
                }
    }
    __syncthreads();

    // ======== epilogue: conv outer product + LeakyReLU + sigmoid ========
    const size_t outb = (size_t)g0 * KER;
    for (int i = tid; i < 128 * 400; i += 512) {
        const int m = i / 400;
        const int j = (i - m * 400) * 4;
        const int n = j / 20;
        const int k = j - n * 20;
        const float hn = h_s[m * HP + n];
        const float cb = scb[n];
        const float4 wv = *(const float4*)&scw[n * KER + k];
        float4 y;
        float t0 = hn * wv.x + cb; t0 = fmaxf(t0, 0.1f * t0); y.x = sigf(t0);
        float t1 = hn * wv.y + cb; t1 = fmaxf(t1, 0.1f * t1); y.y = sigf(t1);
        float t2 = hn * wv.z + cb; t2 = fmaxf(t2, 0.1f * t2); y.z = sigf(t2);
        float t3 = hn * wv.w + cb; t3 = fmaxf(t3, 0.1f * t3); y.w = sigf(t3);
        *(float4*)(out + (size_t)m * ((size_t)NG * KER) + outb + j) = y;
    }
}

extern "C" void kernel_launch(void* const* d_in, const int* in_sizes, int n_in,
                              void* d_out, int out_size) {
    const float* z     = (const float*)d_in[0];
    const float* Wfc   = (const float*)d_in[1];
    // d_in[2] = b_fc: cancelled analytically by BN mean subtraction
    const float* gamma = (const float*)d_in[3];
    const float* beta  = (const float*)d_in[4];
    const float* convw = (const float*)d_in[5];
    const float* convb = (const float*)d_in[6];
    cudaFuncSetAttribute(fused_decoder, cudaFuncAttributeMaxDynamicSharedMemorySize, SMEM_BYTES);
    fused_decoder<<<NCTA, 512, SMEM_BYTES>>>(z, Wfc, gamma, beta, convw, convb, (float*)d_out);
}